// round 7
// baseline (speedup 1.0000x reference)
#include <cuda_runtime.h>
#include <cuda_fp16.h>
#include <cstdint>

#define NPTS 65536
#define MPTS 65536
#define KNB  16
#define NTILES 4096          // MPTS*KNB / 256
#define GRID 148

// ---------------- device scratch (fp16 hi/lo planes) ----------------
__device__ __align__(16) unsigned short g_xhi[(size_t)NPTS * 64];
__device__ __align__(16) unsigned short g_xlo[(size_t)NPTS * 64];
__device__ __align__(16) unsigned short g_w1hi[64 * 64];
__device__ __align__(16) unsigned short g_w1lo[64 * 64];
__device__ __align__(16) unsigned short g_w2hi[128 * 64];
__device__ __align__(16) unsigned short g_w2lo[128 * 64];
__device__ float g_w1pos[64 * 4];
__device__ int   g_idx_is64;

// ---------------- smem layout (bytes) ----------------
#define SM_W1HI 0
#define SM_W1LO 9216
#define SM_W2HI 18432
#define SM_W2LO 36864
#define SM_B1HI 55296
#define SM_B1LO 92160
#define SM_HHI  129024
#define SM_HLO  165888
#define SM_PD   202752
#define SM_W1P  205824
#define SM_POOL 206848
#define SM_TOTAL 217088

// ---------------- helpers ----------------
__device__ __forceinline__ uint32_t smem_u32(const void* p) {
    uint32_t a;
    asm("{ .reg .u64 t; cvta.to.shared.u64 t, %1; cvt.u32.u64 %0, t; }" : "=r"(a) : "l"(p));
    return a;
}
__device__ __forceinline__ void ldsm4(uint32_t (&r)[4], uint32_t addr) {
    asm volatile("ldmatrix.sync.aligned.m8n8.x4.shared.b16 {%0,%1,%2,%3}, [%4];"
                 : "=r"(r[0]), "=r"(r[1]), "=r"(r[2]), "=r"(r[3]) : "r"(addr));
}
// main term: fp16 inputs, fp32 accumulate
__device__ __forceinline__ void mma_f32(float (&d)[4], const uint32_t (&a)[4],
                                        uint32_t b0, uint32_t b1) {
    asm volatile("mma.sync.aligned.m16n8k16.row.col.f32.f16.f16.f32 "
                 "{%0,%1,%2,%3}, {%4,%5,%6,%7}, {%8,%9}, {%0,%1,%2,%3};"
                 : "+f"(d[0]), "+f"(d[1]), "+f"(d[2]), "+f"(d[3])
                 : "r"(a[0]), "r"(a[1]), "r"(a[2]), "r"(a[3]), "r"(b0), "r"(b1));
}
// correction terms: fp16 inputs, fp16 accumulate (2x rate)
__device__ __forceinline__ void mma_f16(uint32_t (&d)[2], const uint32_t (&a)[4],
                                        uint32_t b0, uint32_t b1) {
    asm volatile("mma.sync.aligned.m16n8k16.row.col.f16.f16.f16.f16 "
                 "{%0,%1}, {%2,%3,%4,%5}, {%6,%7}, {%0,%1};"
                 : "+r"(d[0]), "+r"(d[1])
                 : "r"(a[0]), "r"(a[1]), "r"(a[2]), "r"(a[3]), "r"(b0), "r"(b1));
}
__device__ __forceinline__ float lo2f(uint32_t u) {
    __half2 h = *(__half2*)&u; return __low2float(h);
}
__device__ __forceinline__ float hi2f(uint32_t u) {
    __half2 h = *(__half2*)&u; return __high2float(h);
}

// ---------------- single prep kernel ----------------
__global__ __launch_bounds__(256) void prep_all_kernel(const float* __restrict__ x,
                                                       const float* __restrict__ W1,
                                                       const float* __restrict__ W2,
                                                       const unsigned int* __restrict__ idx32)
{
    __shared__ unsigned short shhi[128 * 72];
    __shared__ unsigned short shlo[128 * 72];
    const int p0 = blockIdx.x * 128;
    const int tid = threadIdx.x;

    // x -> fp16 hi/lo, transposed to point-major rows of 128B
    for (int idx = tid; idx < 128 * 64; idx += 256) {
        int c = idx >> 7, p = idx & 127;
        float v = x[(size_t)c * NPTS + p0 + p];
        __half h = __float2half_rn(v);
        __half l = __float2half_rn(v - __half2float(h));
        shhi[p * 72 + c] = __half_as_ushort(h);
        shlo[p * 72 + c] = __half_as_ushort(l);
    }

    if (blockIdx.x == 0) {
        if (tid == 0) {
            unsigned int orv = 0;
            for (int i = 0; i < 256; i++) orv |= idx32[2 * i + 1];
            g_idx_is64 = (orv == 0u) ? 1 : 0;
        }
        for (int i = tid; i < 64 * 64; i += 256) {
            int o = i >> 6, k = i & 63;
            float v = W1[o * 67 + k];
            __half h = __float2half_rn(v);
            __half l = __float2half_rn(v - __half2float(h));
            g_w1hi[i] = __half_as_ushort(h);
            g_w1lo[i] = __half_as_ushort(l);
        }
        if (tid < 64) {
            g_w1pos[tid * 4 + 0] = W1[tid * 67 + 64];
            g_w1pos[tid * 4 + 1] = W1[tid * 67 + 65];
            g_w1pos[tid * 4 + 2] = W1[tid * 67 + 66];
            g_w1pos[tid * 4 + 3] = 0.0f;
        }
        for (int i = tid; i < 128 * 64; i += 256) {
            float v = W2[i];
            __half h = __float2half_rn(v);
            __half l = __float2half_rn(v - __half2float(h));
            g_w2hi[i] = __half_as_ushort(h);
            g_w2lo[i] = __half_as_ushort(l);
        }
    }
    __syncthreads();
    uint4* dh = (uint4*)(g_xhi + (size_t)p0 * 64);
    uint4* dl = (uint4*)(g_xlo + (size_t)p0 * 64);
    for (int i = tid; i < 1024; i += 256) {
        int p = i >> 3, q = i & 7;
        dh[i] = *(const uint4*)&shhi[p * 72 + q * 8];
        dl[i] = *(const uint4*)&shlo[p * 72 + q * 8];
    }
}

// ---------------- main persistent kernel ----------------
extern __shared__ char smc[];

__global__ __launch_bounds__(512, 1)
void pointnet_mma_kernel(const float* __restrict__ pos,
                         const float* __restrict__ sup,
                         const float* __restrict__ b1,
                         const float* __restrict__ b2,
                         const void* __restrict__ indices,
                         float* __restrict__ out)
{
    const uint32_t sb = smem_u32(smc);
    const int tid = threadIdx.x;
    const int w = tid >> 5;
    const int l = tid & 31;
    const int is64 = g_idx_is64;

    // ---- stage weights once ----
    for (int i = tid; i < 1024; i += 512) {          // W1 hi/lo
        int buf = i >> 9, o = (i >> 3) & 63, c = i & 7;
        const uint4* s = (const uint4*)((buf ? g_w1lo : g_w1hi) + o * 64);
        *(uint4*)(smc + SM_W1HI + buf * 9216 + o * 144 + c * 16) = s[c];
    }
    for (int i = tid; i < 2048; i += 512) {          // W2 hi/lo
        int buf = i >> 10, o = (i >> 3) & 127, c = i & 7;
        const uint4* s = (const uint4*)((buf ? g_w2lo : g_w2hi) + o * 64);
        *(uint4*)(smc + SM_W2HI + buf * 18432 + o * 144 + c * 16) = s[c];
    }
    if (tid < 256) *(float*)(smc + SM_W1P + tid * 4) = g_w1pos[tid];
    __syncthreads();

    float* pdf   = (float*)(smc + SM_PD);
    float* poolf = (float*)(smc + SM_POOL);

    for (int tile = blockIdx.x; tile < NTILES; tile += gridDim.x) {
        // ================= gather =================
        {
            const int gg = l >> 3, cc = l & 7;
#pragma unroll
            for (int it = 0; it < 4; it++) {
                int p = it * 64 + w * 4 + gg;
                long long lin = (long long)tile * 256 + p;
                int ii;
                if (is64) ii = (int)((const long long*)indices)[lin] & (NPTS - 1);
                else      ii = ((const int*)indices)[lin] & (NPTS - 1);
                const uint4* sh = (const uint4*)(g_xhi + (size_t)ii * 64);
                const uint4* sl = (const uint4*)(g_xlo + (size_t)ii * 64);
                *(uint4*)(smc + SM_B1HI + p * 144 + cc * 16) = sh[cc];
                *(uint4*)(smc + SM_B1LO + p * 144 + cc * 16) = sl[cc];
            }
            if (tid < 256) {
                int p = tid;
                long long lin = (long long)tile * 256 + p;
                int ii;
                if (is64) ii = (int)((const long long*)indices)[lin] & (NPTS - 1);
                else      ii = ((const int*)indices)[lin] & (NPTS - 1);
                int m = tile * 16 + (p >> 4);
#pragma unroll
                for (int d = 0; d < 3; d++)
                    pdf[d * 256 + p] = pos[d * NPTS + ii] - sup[d * MPTS + m];
            }
        }
        __syncthreads();

        // ================= GEMM1: 64 x 256, K=64 =================
        {
            const int wm = w & 3, wn = w >> 2;
            const int o0 = wm * 16;
            float    accm[8][4];
            uint32_t accc[8][2];
#pragma unroll
            for (int i = 0; i < 8; i++) {
#pragma unroll
                for (int j = 0; j < 4; j++) accm[i][j] = 0.0f;
                accc[i][0] = 0u; accc[i][1] = 0u;
            }

            const uint32_t arowH = sb + SM_W1HI +
                (o0 + ((l >> 3) & 1) * 8 + (l & 7)) * 144;
            const uint32_t arowL = arowH + 9216;
            const uint32_t browH = sb + SM_B1HI +
                (wn * 64 + ((l >> 4) & 1) * 8 + (l & 7)) * 144;
            const uint32_t browL = browH + 36864;

#pragma unroll
            for (int ks = 0; ks < 4; ks++) {
                uint32_t ach = (2 * ks + (l >> 4)) * 16;
                uint32_t bch = (2 * ks + ((l >> 3) & 1)) * 16;
                uint32_t ah[4], al[4];
                ldsm4(ah, arowH + ach);
                ldsm4(al, arowL + ach);
#pragma unroll
                for (int nbp = 0; nbp < 4; nbp++) {
                    uint32_t bh[4], bl[4];
                    ldsm4(bh, browH + nbp * (16 * 144) + bch);
                    mma_f32(accm[2 * nbp],     ah, bh[0], bh[1]);
                    mma_f32(accm[2 * nbp + 1], ah, bh[2], bh[3]);
                    mma_f16(accc[2 * nbp],     al, bh[0], bh[1]);
                    mma_f16(accc[2 * nbp + 1], al, bh[2], bh[3]);
                    ldsm4(bl, browL + nbp * (16 * 144) + bch);
                    mma_f16(accc[2 * nbp],     ah, bl[0], bl[1]);
                    mma_f16(accc[2 * nbp + 1], ah, bl[2], bl[3]);
                }
            }

            // ---- epilogue 1: corr + pos-term + bias + relu -> H hi/lo ----
            const int o_lo = o0 + (l >> 2);
            const int o_hi = o_lo + 8;
            float4 wpl = *(const float4*)(smc + SM_W1P + o_lo * 16);
            float4 wph = *(const float4*)(smc + SM_W1P + o_hi * 16);
            float bl_ = __ldg(&b1[o_lo]);
            float bh_ = __ldg(&b1[o_hi]);
            const int paired = (((l >> 2) & 1) == 0);

#pragma unroll
            for (int nb = 0; nb < 8; nb++) {
                int cb = wn * 64 + nb * 8 + (l & 3) * 2;
                float2 q0 = *(const float2*)&pdf[0 * 256 + cb];
                float2 q1 = *(const float2*)&pdf[1 * 256 + cb];
                float2 q2 = *(const float2*)&pdf[2 * 256 + cb];
                float v[4];
                v[0] = fmaxf(accm[nb][0] + lo2f(accc[nb][0]) + bl_ + wpl.x * q0.x + wpl.y * q1.x + wpl.z * q2.x, 0.0f);
                v[1] = fmaxf(accm[nb][1] + hi2f(accc[nb][0]) + bl_ + wpl.x * q0.y + wpl.y * q1.y + wpl.z * q2.y, 0.0f);
                v[2] = fmaxf(accm[nb][2] + lo2f(accc[nb][1]) + bh_ + wph.x * q0.x + wph.y * q1.x + wph.z * q2.x, 0.0f);
                v[3] = fmaxf(accm[nb][3] + hi2f(accc[nb][1]) + bh_ + wph.x * q0.y + wph.y * q1.y + wph.z * q2.y, 0.0f);
                const int colv[4] = {cb, cb + 1, cb, cb + 1};
                const int ov[4]   = {o_lo, o_lo, o_hi, o_hi};
#pragma unroll
                for (int q = 0; q < 4; q++) {
                    __half hb = __float2half_rn(v[q]);
                    float rem = v[q] - __half2float(hb);
                    __half lb = __float2half_rn(rem);
                    uint32_t uh = (uint32_t)__half_as_ushort(hb);
                    uint32_t ul = (uint32_t)__half_as_ushort(lb);
                    uint32_t ph = __shfl_xor_sync(0xffffffffu, uh, 4);
                    uint32_t pl = __shfl_xor_sync(0xffffffffu, ul, 4);
                    if (paired) {
                        uint32_t off = colv[q] * 144 + ov[q] * 2;
                        *(uint32_t*)(smc + SM_HHI + off) = uh | (ph << 16);
                        *(uint32_t*)(smc + SM_HLO + off) = ul | (pl << 16);
                    }
                }
            }
        }
        __syncthreads();

        // ================= GEMM2: 128 x 256, K=64 + max-pool =================
        {
            const int wm = w & 7, wn = w >> 3;
            const int o0 = wm * 16;
            float    accm[16][4];
            uint32_t accc[16][2];
#pragma unroll
            for (int i = 0; i < 16; i++) {
#pragma unroll
                for (int j = 0; j < 4; j++) accm[i][j] = 0.0f;
                accc[i][0] = 0u; accc[i][1] = 0u;
            }

            const uint32_t arowH = sb + SM_W2HI +
                (o0 + ((l >> 3) & 1) * 8 + (l & 7)) * 144;
            const uint32_t arowL = arowH + 18432;
            const uint32_t browH = sb + SM_HHI +
                (wn * 128 + ((l >> 4) & 1) * 8 + (l & 7)) * 144;
            const uint32_t browL = browH + 36864;

#pragma unroll
            for (int ks = 0; ks < 4; ks++) {
                uint32_t ach = (2 * ks + (l >> 4)) * 16;
                uint32_t bch = (2 * ks + ((l >> 3) & 1)) * 16;
                uint32_t ah[4], al[4];
                ldsm4(ah, arowH + ach);
                ldsm4(al, arowL + ach);
#pragma unroll
                for (int nbp = 0; nbp < 8; nbp++) {
                    uint32_t bh[4], bl[4];
                    ldsm4(bh, browH + nbp * (16 * 144) + bch);
                    mma_f32(accm[2 * nbp],     ah, bh[0], bh[1]);
                    mma_f32(accm[2 * nbp + 1], ah, bh[2], bh[3]);
                    mma_f16(accc[2 * nbp],     al, bh[0], bh[1]);
                    mma_f16(accc[2 * nbp + 1], al, bh[2], bh[3]);
                    ldsm4(bl, browL + nbp * (16 * 144) + bch);
                    mma_f16(accc[2 * nbp],     ah, bl[0], bl[1]);
                    mma_f16(accc[2 * nbp + 1], ah, bl[2], bl[3]);
                }
            }

            // ---- pool over K=16 ----
#pragma unroll
            for (int nbp = 0; nbp < 8; nbp++) {
                float a0 = accm[2 * nbp][0]     + lo2f(accc[2 * nbp][0]);
                float a1 = accm[2 * nbp][1]     + hi2f(accc[2 * nbp][0]);
                float b0 = accm[2 * nbp + 1][0] + lo2f(accc[2 * nbp + 1][0]);
                float b1v = accm[2 * nbp + 1][1] + hi2f(accc[2 * nbp + 1][0]);
                float a2 = accm[2 * nbp][2]     + lo2f(accc[2 * nbp][1]);
                float a3 = accm[2 * nbp][3]     + hi2f(accc[2 * nbp][1]);
                float b2v = accm[2 * nbp + 1][2] + lo2f(accc[2 * nbp + 1][1]);
                float b3 = accm[2 * nbp + 1][3] + hi2f(accc[2 * nbp + 1][1]);
                float mlo = fmaxf(fmaxf(a0, a1), fmaxf(b0, b1v));
                float mhi = fmaxf(fmaxf(a2, a3), fmaxf(b2v, b3));
                mlo = fmaxf(mlo, __shfl_xor_sync(0xffffffffu, mlo, 1));
                mlo = fmaxf(mlo, __shfl_xor_sync(0xffffffffu, mlo, 2));
                mhi = fmaxf(mhi, __shfl_xor_sync(0xffffffffu, mhi, 1));
                mhi = fmaxf(mhi, __shfl_xor_sync(0xffffffffu, mhi, 2));
                if ((l & 3) == 0) {
                    int mp = wn * 8 + nbp;
                    poolf[(o0 + (l >> 2)) * 20 + mp]     = mlo;
                    poolf[(o0 + 8 + (l >> 2)) * 20 + mp] = mhi;
                }
            }
        }
        __syncthreads();

        // ---- coalesced output: [o][m], +b2 ----
        {
            int o = tid >> 2, mg = tid & 3;
            float4 v = *(const float4*)(poolf + o * 20 + mg * 4);
            float bb = __ldg(&b2[o]);
            v.x += bb; v.y += bb; v.z += bb; v.w += bb;
            *(float4*)(out + (size_t)o * MPTS + tile * 16 + mg * 4) = v;
        }
        __syncthreads();
    }
}

// ---------------------------------------------------------------------------
extern "C" void kernel_launch(void* const* d_in, const int* in_sizes, int n_in,
                              void* d_out, int out_size)
{
    const float *x = 0, *pos = 0, *sup = 0, *W1 = 0, *b1 = 0, *W2 = 0, *b2 = 0;
    const void* idx = 0;
    for (int i = 0; i < n_in; i++) {
        switch (in_sizes[i]) {
            case 4194304: x  = (const float*)d_in[i]; break;
            case 196608:  if (!pos) pos = (const float*)d_in[i];
                          else      sup = (const float*)d_in[i]; break;
            case 4288:    W1 = (const float*)d_in[i]; break;
            case 64:      b1 = (const float*)d_in[i]; break;
            case 8192:    W2 = (const float*)d_in[i]; break;
            case 128:     b2 = (const float*)d_in[i]; break;
            case 1048576: idx = d_in[i]; break;
            default: break;
        }
    }
    float* out = (float*)d_out;

    prep_all_kernel<<<NPTS / 128, 256>>>(x, W1, W2, (const unsigned int*)idx);

    cudaFuncSetAttribute(pointnet_mma_kernel,
                         cudaFuncAttributeMaxDynamicSharedMemorySize, SM_TOTAL);
    pointnet_mma_kernel<<<GRID, 512, SM_TOTAL>>>(pos, sup, b1, b2, idx, out);
}

// round 8
// speedup vs baseline: 1.6259x; 1.6259x over previous
#include <cuda_runtime.h>
#include <cuda_fp16.h>
#include <cstdint>

#define NPTS 65536
#define MPTS 65536
#define KNB  16
#define TILE 128              // columns per CTA tile (8 pts x 16 nbrs)
#define NTILES 8192
#define GRID 296              // 2 CTAs per SM

// ---------------- device scratch ----------------
__device__ __align__(16) unsigned short g_xhi[(size_t)NPTS * 64];   // fp16 rows 128B
__device__ __align__(16) unsigned short g_w1hi[64 * 64];
__device__ __align__(16) unsigned short g_w1lo[64 * 64];
__device__ __align__(16) unsigned short g_w2hi[128 * 64];
__device__ __align__(16) unsigned short g_w2lo[128 * 64];
__device__ float g_w1pos[64 * 4];
__device__ int   g_idx_is64;

// ---------------- smem layout (bytes) ----------------
#define SM_W1HI 0
#define SM_W1LO 9216
#define SM_W2HI 18432
#define SM_W2LO 36864
#define SM_B1   55296          // 128 * 144 (hi only)
#define SM_H    73728          // 128 * 144 (hi only)
#define SM_PD   92160          // 3 * 128 * 4
#define SM_W1P  93696          // 64 * 16
#define SM_POOL 94720          // 128 * 12 * 4
#define SM_TOTAL 100864

// ---------------- helpers ----------------
__device__ __forceinline__ uint32_t smem_u32(const void* p) {
    uint32_t a;
    asm("{ .reg .u64 t; cvta.to.shared.u64 t, %1; cvt.u32.u64 %0, t; }" : "=r"(a) : "l"(p));
    return a;
}
__device__ __forceinline__ void ldsm4(uint32_t (&r)[4], uint32_t addr) {
    asm volatile("ldmatrix.sync.aligned.m8n8.x4.shared.b16 {%0,%1,%2,%3}, [%4];"
                 : "=r"(r[0]), "=r"(r[1]), "=r"(r[2]), "=r"(r[3]) : "r"(addr));
}
__device__ __forceinline__ void mma_f32(float (&d)[4], const uint32_t (&a)[4],
                                        uint32_t b0, uint32_t b1) {
    asm volatile("mma.sync.aligned.m16n8k16.row.col.f32.f16.f16.f32 "
                 "{%0,%1,%2,%3}, {%4,%5,%6,%7}, {%8,%9}, {%0,%1,%2,%3};"
                 : "+f"(d[0]), "+f"(d[1]), "+f"(d[2]), "+f"(d[3])
                 : "r"(a[0]), "r"(a[1]), "r"(a[2]), "r"(a[3]), "r"(b0), "r"(b1));
}

// ---------------- prep ----------------
__global__ __launch_bounds__(256) void prep_all_kernel(const float* __restrict__ x,
                                                       const float* __restrict__ W1,
                                                       const float* __restrict__ W2,
                                                       const unsigned int* __restrict__ idx32)
{
    __shared__ unsigned short shhi[128 * 72];
    const int p0 = blockIdx.x * 128;
    const int tid = threadIdx.x;

    for (int idx = tid; idx < 128 * 64; idx += 256) {
        int c = idx >> 7, p = idx & 127;
        float v = x[(size_t)c * NPTS + p0 + p];
        shhi[p * 72 + c] = __half_as_ushort(__float2half_rn(v));
    }

    if (blockIdx.x == 0) {
        if (tid == 0) {
            unsigned int orv = 0;
            for (int i = 0; i < 256; i++) orv |= idx32[2 * i + 1];
            g_idx_is64 = (orv == 0u) ? 1 : 0;
        }
        for (int i = tid; i < 64 * 64; i += 256) {
            int o = i >> 6, k = i & 63;
            float v = W1[o * 67 + k];
            __half h = __float2half_rn(v);
            __half lo = __float2half_rn(v - __half2float(h));
            g_w1hi[i] = __half_as_ushort(h);
            g_w1lo[i] = __half_as_ushort(lo);
        }
        if (tid < 64) {
            g_w1pos[tid * 4 + 0] = W1[tid * 67 + 64];
            g_w1pos[tid * 4 + 1] = W1[tid * 67 + 65];
            g_w1pos[tid * 4 + 2] = W1[tid * 67 + 66];
            g_w1pos[tid * 4 + 3] = 0.0f;
        }
        for (int i = tid; i < 128 * 64; i += 256) {
            float v = W2[i];
            __half h = __float2half_rn(v);
            __half lo = __float2half_rn(v - __half2float(h));
            g_w2hi[i] = __half_as_ushort(h);
            g_w2lo[i] = __half_as_ushort(lo);
        }
    }
    __syncthreads();
    uint4* dh = (uint4*)(g_xhi + (size_t)p0 * 64);
    for (int i = tid; i < 1024; i += 256) {
        int p = i >> 3, q = i & 7;
        dh[i] = *(const uint4*)&shhi[p * 72 + q * 8];
    }
}

// ---------------- main persistent kernel: 256 thr, 2 CTAs/SM ----------------
extern __shared__ char smc[];

__global__ __launch_bounds__(256, 2)
void pointnet_mma_kernel(const float* __restrict__ pos,
                         const float* __restrict__ sup,
                         const float* __restrict__ b1,
                         const float* __restrict__ b2,
                         const void* __restrict__ indices,
                         float* __restrict__ out)
{
    const uint32_t sb = smem_u32(smc);
    const int tid = threadIdx.x;
    const int w = tid >> 5;
    const int l = tid & 31;
    const int is64 = g_idx_is64;

    // ---- stage weights once ----
    for (int i = tid; i < 1024; i += 256) {          // W1 hi/lo
        int buf = i >> 9, o = (i >> 3) & 63, c = i & 7;
        const uint4* s = (const uint4*)((buf ? g_w1lo : g_w1hi) + o * 64);
        *(uint4*)(smc + SM_W1HI + buf * 9216 + o * 144 + c * 16) = s[c];
    }
    for (int i = tid; i < 2048; i += 256) {          // W2 hi/lo
        int buf = i >> 10, o = (i >> 3) & 127, c = i & 7;
        const uint4* s = (const uint4*)((buf ? g_w2lo : g_w2hi) + o * 64);
        *(uint4*)(smc + SM_W2HI + buf * 18432 + o * 144 + c * 16) = s[c];
    }
    if (tid < 256) *(float*)(smc + SM_W1P + tid * 4) = g_w1pos[tid];
    __syncthreads();

    float* pdf   = (float*)(smc + SM_PD);
    float* poolf = (float*)(smc + SM_POOL);

    // ---- loop-invariant per-thread constants ----
    const int wm1 = w & 3, wn1 = w >> 2;             // GEMM1 mapping
    const int o0_1 = wm1 * 16;
    const int o_lo = o0_1 + (l >> 2);
    const int o_hi = o_lo + 8;
    const float4 wpl = *(const float4*)(smc + SM_W1P + o_lo * 16);
    const float4 wph = *(const float4*)(smc + SM_W1P + o_hi * 16);
    const float bl_ = __ldg(&b1[o_lo]);
    const float bh_ = __ldg(&b1[o_hi]);
    const int paired = (((l >> 2) & 1) == 0);
    const int o0_2 = w * 16;                          // GEMM2 mapping
    const float bb_out = __ldg(&b2[tid >> 1]);

    const uint32_t arow1H = sb + SM_W1HI + (o0_1 + ((l >> 3) & 1) * 8 + (l & 7)) * 144;
    const uint32_t arow1L = arow1H + 9216;
    const uint32_t brow1  = sb + SM_B1 + (wn1 * 64 + ((l >> 4) & 1) * 8 + (l & 7)) * 144;
    const uint32_t arow2H = sb + SM_W2HI + (o0_2 + ((l >> 3) & 1) * 8 + (l & 7)) * 144;
    const uint32_t arow2L = arow2H + 18432;
    const uint32_t brow2  = sb + SM_H + (((l >> 4) & 1) * 8 + (l & 7)) * 144;

    const int gp   = tid >> 1;                        // gather: row
    const int half = tid & 1;                         // gather: chunk half

    for (int tile = blockIdx.x; tile < NTILES; tile += GRID) {
        // ================= gather (hi plane only) =================
        {
            long long lin = (long long)tile * TILE + gp;
            int ii;
            if (is64) ii = (int)((const long long*)indices)[lin] & (NPTS - 1);
            else      ii = ((const int*)indices)[lin] & (NPTS - 1);
            const uint4* src = (const uint4*)(g_xhi + (size_t)ii * 64);
#pragma unroll
            for (int q = 0; q < 4; q++) {
                int c = half * 4 + q;
                *(uint4*)(smc + SM_B1 + gp * 144 + c * 16) = src[c];
            }
            if (tid < TILE) {
                long long lin2 = (long long)tile * TILE + tid;
                int ii2;
                if (is64) ii2 = (int)((const long long*)indices)[lin2] & (NPTS - 1);
                else      ii2 = ((const int*)indices)[lin2] & (NPTS - 1);
                int m = tile * 8 + (tid >> 4);
#pragma unroll
                for (int d = 0; d < 3; d++)
                    pdf[d * TILE + tid] = pos[d * NPTS + ii2] - sup[d * MPTS + m];
            }
        }
        __syncthreads();

        // ================= GEMM1: 64 x 128, K=64 =================
        {
            float acc[8][4];
#pragma unroll
            for (int i = 0; i < 8; i++)
#pragma unroll
                for (int j = 0; j < 4; j++) acc[i][j] = 0.0f;

#pragma unroll
            for (int ks = 0; ks < 4; ks++) {
                uint32_t ach = (2 * ks + (l >> 4)) * 16;
                uint32_t bch = (2 * ks + ((l >> 3) & 1)) * 16;
                uint32_t ah[4], al[4];
                ldsm4(ah, arow1H + ach);
                ldsm4(al, arow1L + ach);
#pragma unroll
                for (int nbp = 0; nbp < 4; nbp++) {
                    uint32_t bh[4];
                    ldsm4(bh, brow1 + nbp * (16 * 144) + bch);
                    mma_f32(acc[2 * nbp],     ah, bh[0], bh[1]);
                    mma_f32(acc[2 * nbp + 1], ah, bh[2], bh[3]);
                    mma_f32(acc[2 * nbp],     al, bh[0], bh[1]);
                    mma_f32(acc[2 * nbp + 1], al, bh[2], bh[3]);
                }
            }

            // ---- epilogue 1: pos-term + bias + relu -> H (fp16 hi only) ----
#pragma unroll
            for (int nb = 0; nb < 8; nb++) {
                int cb = wn1 * 64 + nb * 8 + (l & 3) * 2;
                float2 q0 = *(const float2*)&pdf[0 * TILE + cb];
                float2 q1 = *(const float2*)&pdf[1 * TILE + cb];
                float2 q2 = *(const float2*)&pdf[2 * TILE + cb];
                float v[4];
                v[0] = fmaxf(acc[nb][0] + bl_ + wpl.x * q0.x + wpl.y * q1.x + wpl.z * q2.x, 0.0f);
                v[1] = fmaxf(acc[nb][1] + bl_ + wpl.x * q0.y + wpl.y * q1.y + wpl.z * q2.y, 0.0f);
                v[2] = fmaxf(acc[nb][2] + bh_ + wph.x * q0.x + wph.y * q1.x + wph.z * q2.x, 0.0f);
                v[3] = fmaxf(acc[nb][3] + bh_ + wph.x * q0.y + wph.y * q1.y + wph.z * q2.y, 0.0f);
                const int colv[4] = {cb, cb + 1, cb, cb + 1};
                const int ov[4]   = {o_lo, o_lo, o_hi, o_hi};
#pragma unroll
                for (int q = 0; q < 4; q++) {
                    uint32_t uh = (uint32_t)__half_as_ushort(__float2half_rn(v[q]));
                    uint32_t ph = __shfl_xor_sync(0xffffffffu, uh, 4);
                    if (paired) {
                        uint32_t off = colv[q] * 144 + ov[q] * 2;
                        *(uint32_t*)(smc + SM_H + off) = uh | (ph << 16);
                    }
                }
            }
        }
        __syncthreads();

        // ================= GEMM2: 128 x 128, K=64 + max-pool =================
        {
            float acc[16][4];
#pragma unroll
            for (int i = 0; i < 16; i++)
#pragma unroll
                for (int j = 0; j < 4; j++) acc[i][j] = 0.0f;

#pragma unroll
            for (int ks = 0; ks < 4; ks++) {
                uint32_t ach = (2 * ks + (l >> 4)) * 16;
                uint32_t bch = (2 * ks + ((l >> 3) & 1)) * 16;
                uint32_t ah[4], al[4];
                ldsm4(ah, arow2H + ach);
                ldsm4(al, arow2L + ach);
#pragma unroll
                for (int nbp = 0; nbp < 8; nbp++) {
                    uint32_t bh[4];
                    ldsm4(bh, brow2 + nbp * (16 * 144) + bch);
                    mma_f32(acc[2 * nbp],     ah, bh[0], bh[1]);
                    mma_f32(acc[2 * nbp + 1], ah, bh[2], bh[3]);
                    mma_f32(acc[2 * nbp],     al, bh[0], bh[1]);
                    mma_f32(acc[2 * nbp + 1], al, bh[2], bh[3]);
                }
            }

            // ---- pool over K=16 (one m-group per nbp) ----
#pragma unroll
            for (int nbp = 0; nbp < 8; nbp++) {
                float mlo = fmaxf(fmaxf(acc[2 * nbp][0], acc[2 * nbp][1]),
                                  fmaxf(acc[2 * nbp + 1][0], acc[2 * nbp + 1][1]));
                float mhi = fmaxf(fmaxf(acc[2 * nbp][2], acc[2 * nbp][3]),
                                  fmaxf(acc[2 * nbp + 1][2], acc[2 * nbp + 1][3]));
                mlo = fmaxf(mlo, __shfl_xor_sync(0xffffffffu, mlo, 1));
                mlo = fmaxf(mlo, __shfl_xor_sync(0xffffffffu, mlo, 2));
                mhi = fmaxf(mhi, __shfl_xor_sync(0xffffffffu, mhi, 1));
                mhi = fmaxf(mhi, __shfl_xor_sync(0xffffffffu, mhi, 2));
                if ((l & 3) == 0) {
                    poolf[(o0_2 + (l >> 2)) * 12 + nbp]     = mlo;
                    poolf[(o0_2 + 8 + (l >> 2)) * 12 + nbp] = mhi;
                }
            }
        }
        __syncthreads();

        // ---- coalesced output: [o][m], +b2 ----
        {
            int o = tid >> 1, mg = tid & 1;
            float4 v = *(const float4*)(poolf + o * 12 + mg * 4);
            v.x += bb_out; v.y += bb_out; v.z += bb_out; v.w += bb_out;
            *(float4*)(out + (size_t)o * MPTS + tile * 8 + mg * 4) = v;
        }
        __syncthreads();
    }
}

// ---------------------------------------------------------------------------
extern "C" void kernel_launch(void* const* d_in, const int* in_sizes, int n_in,
                              void* d_out, int out_size)
{
    const float *x = 0, *pos = 0, *sup = 0, *W1 = 0, *b1 = 0, *W2 = 0, *b2 = 0;
    const void* idx = 0;
    for (int i = 0; i < n_in; i++) {
        switch (in_sizes[i]) {
            case 4194304: x  = (const float*)d_in[i]; break;
            case 196608:  if (!pos) pos = (const float*)d_in[i];
                          else      sup = (const float*)d_in[i]; break;
            case 4288:    W1 = (const float*)d_in[i]; break;
            case 64:      b1 = (const float*)d_in[i]; break;
            case 8192:    W2 = (const float*)d_in[i]; break;
            case 128:     b2 = (const float*)d_in[i]; break;
            case 1048576: idx = d_in[i]; break;
            default: break;
        }
    }
    float* out = (float*)d_out;

    prep_all_kernel<<<NPTS / 128, 256>>>(x, W1, W2, (const unsigned int*)idx);

    cudaFuncSetAttribute(pointnet_mma_kernel,
                         cudaFuncAttributeMaxDynamicSharedMemorySize, SM_TOTAL);
    pointnet_mma_kernel<<<GRID, 256, SM_TOTAL>>>(pos, sup, b1, b2, idx, out);
}

// round 9
// speedup vs baseline: 2.1407x; 1.3166x over previous
#include <cuda_runtime.h>
#include <cuda_fp16.h>
#include <cstdint>

#define NPTS 65536
#define MPTS 65536
#define KNB  16
#define TILE 128              // columns per CTA tile (8 pts x 16 nbrs)
#define NTILES 8192
#define GRID 296              // 2 CTAs per SM

// ---------------- device scratch ----------------
__device__ __align__(16) unsigned short g_x[(size_t)NPTS * 64];    // fp16 rows 128B
__device__ __align__(16) unsigned short g_w1e[64 * 80];            // W1|pos|bias|pad
__device__ __align__(16) unsigned short g_w2[128 * 64];
__device__ int g_idx_is64;

// ---------------- smem layout (bytes) ----------------
// strides: B1/W1 rows 176B (K=80), H/W2 rows 144B (K=64) — odd multiples of 16B
#define SM_W1   0                      // 64 * 176 = 11264
#define SM_W2   11264                  // 128 * 144 = 18432
#define SM_B1   29696                  // 128 * 176 = 22528
#define SM_H    52224                  // 128 * 144 = 18432
#define SM_POOL 70656                  // 128 * 12 * 4 = 6144
#define SM_TOTAL 76800

// ---------------- helpers ----------------
__device__ __forceinline__ uint32_t smem_u32(const void* p) {
    uint32_t a;
    asm("{ .reg .u64 t; cvta.to.shared.u64 t, %1; cvt.u32.u64 %0, t; }" : "=r"(a) : "l"(p));
    return a;
}
__device__ __forceinline__ void ldsm4(uint32_t (&r)[4], uint32_t addr) {
    asm volatile("ldmatrix.sync.aligned.m8n8.x4.shared.b16 {%0,%1,%2,%3}, [%4];"
                 : "=r"(r[0]), "=r"(r[1]), "=r"(r[2]), "=r"(r[3]) : "r"(addr));
}
__device__ __forceinline__ void mma_f32(float (&d)[4], const uint32_t (&a)[4],
                                        uint32_t b0, uint32_t b1) {
    asm volatile("mma.sync.aligned.m16n8k16.row.col.f32.f16.f16.f32 "
                 "{%0,%1,%2,%3}, {%4,%5,%6,%7}, {%8,%9}, {%0,%1,%2,%3};"
                 : "+f"(d[0]), "+f"(d[1]), "+f"(d[2]), "+f"(d[3])
                 : "r"(a[0]), "r"(a[1]), "r"(a[2]), "r"(a[3]), "r"(b0), "r"(b1));
}
#define CP16(dst, src) \
    asm volatile("cp.async.cg.shared.global [%0], [%1], 16;" :: "r"(dst), "l"(src))
#define CP_COMMIT()  asm volatile("cp.async.commit_group;" ::: "memory")
#define CP_WAIT0()   asm volatile("cp.async.wait_group 0;" ::: "memory")

__device__ __forceinline__ uint32_t packh2(float a, float b) {
    __half2 h = __floats2half2_rn(a, b);
    return *(uint32_t*)&h;
}

// ---------------- prep ----------------
__global__ __launch_bounds__(256) void prep_all_kernel(const float* __restrict__ x,
                                                       const float* __restrict__ W1,
                                                       const float* __restrict__ b1,
                                                       const float* __restrict__ W2,
                                                       const unsigned int* __restrict__ idx32)
{
    __shared__ unsigned short shhi[128 * 72];
    const int p0 = blockIdx.x * 128;
    const int tid = threadIdx.x;

    for (int idx = tid; idx < 128 * 64; idx += 256) {
        int c = idx >> 7, p = idx & 127;
        float v = x[(size_t)c * NPTS + p0 + p];
        shhi[p * 72 + c] = __half_as_ushort(__float2half_rn(v));
    }

    if (blockIdx.x == 0) {
        if (tid == 0) {
            unsigned int orv = 0;
            for (int i = 0; i < 256; i++) orv |= idx32[2 * i + 1];
            g_idx_is64 = (orv == 0u) ? 1 : 0;
        }
        // W1 extended: [o][c]: c<67 -> W1, c==67 -> b1, else 0
        for (int i = tid; i < 64 * 80; i += 256) {
            int o = i / 80, c = i % 80;
            float v = 0.0f;
            if (c < 67)       v = W1[o * 67 + c];
            else if (c == 67) v = b1[o];
            g_w1e[i] = __half_as_ushort(__float2half_rn(v));
        }
        for (int i = tid; i < 128 * 64; i += 256)
            g_w2[i] = __half_as_ushort(__float2half_rn(W2[i]));
    }
    __syncthreads();
    uint4* dh = (uint4*)(g_x + (size_t)p0 * 64);
    for (int i = tid; i < 1024; i += 256) {
        int p = i >> 3, q = i & 7;
        dh[i] = *(const uint4*)&shhi[p * 72 + q * 8];
    }
}

// ---------------- main persistent kernel: 256 thr, 2 CTAs/SM ----------------
extern __shared__ char smc[];

__global__ __launch_bounds__(256, 2)
void pointnet_mma_kernel(const float* __restrict__ pos,
                         const float* __restrict__ sup,
                         const float* __restrict__ b2,
                         const void* __restrict__ indices,
                         float* __restrict__ out)
{
    const uint32_t sb = smem_u32(smc);
    const int tid = threadIdx.x;
    const int w = tid >> 5;
    const int l = tid & 31;
    const int is64 = g_idx_is64;

    // ---- stage weights once ----
    for (int i = tid; i < 640; i += 256) {            // W1e: 64 rows x 10 chunks
        int o = i / 10, c = i % 10;
        *(uint4*)(smc + SM_W1 + o * 176 + c * 16) = *(const uint4*)(g_w1e + o * 80 + c * 8);
    }
    for (int i = tid; i < 1024; i += 256) {           // W2: 128 rows x 8 chunks
        int o = i >> 3, c = i & 7;
        *(uint4*)(smc + SM_W2 + o * 144 + c * 16) = *(const uint4*)(g_w2 + o * 64 + c * 8);
    }
    __syncthreads();

    float* poolf = (float*)(smc + SM_POOL);

    // ---- loop-invariant constants ----
    // GEMM1: mw=2 (w&1), nw=4 (w>>1)
    const uint32_t arow1 = sb + SM_W1 + (32 * (w & 1) + ((l >> 3) & 1) * 8 + (l & 7)) * 176;
    const uint32_t brow1 = sb + SM_B1 + (32 * (w >> 1) + ((l >> 4) & 1) * 8 + (l & 7)) * 176;
    // GEMM2: mw=4 (w&3), nw=2 (w>>2)
    const uint32_t arow2 = sb + SM_W2 + (32 * (w & 3) + ((l >> 3) & 1) * 8 + (l & 7)) * 144;
    const uint32_t brow2 = sb + SM_H  + (64 * (w >> 2) + ((l >> 4) & 1) * 8 + (l & 7)) * 144;

    const int ch_lo = 32 * (w & 1) + (l >> 2);        // +16*mb at use
    const int paired = (((l >> 2) & 1) == 0);
    const float bb_out = __ldg(&b2[tid >> 1]);

    const int gp   = tid >> 1;                        // gather row
    const int half = tid & 1;

    for (int tile = blockIdx.x; tile < NTILES; tile += GRID) {
        // ================= gather (cp.async, hi plane) =================
        {
            long long lin = (long long)tile * TILE + gp;
            int ii;
            if (is64) ii = (int)((const long long*)indices)[lin] & (NPTS - 1);
            else      ii = ((const int*)indices)[lin] & (NPTS - 1);
            const char* src = (const char*)g_x + (size_t)ii * 128;
            uint32_t dst = sb + SM_B1 + gp * 176 + half * 64;
#pragma unroll
            for (int q = 0; q < 4; q++)
                CP16(dst + q * 16, src + half * 64 + q * 16);
            CP_COMMIT();

            if (tid < TILE) {
                long long lin2 = (long long)tile * TILE + tid;
                int ii2;
                if (is64) ii2 = (int)((const long long*)indices)[lin2] & (NPTS - 1);
                else      ii2 = ((const int*)indices)[lin2] & (NPTS - 1);
                int m = tile * 8 + (tid >> 4);
                float p0 = pos[0 * NPTS + ii2] - sup[0 * MPTS + m];
                float p1 = pos[1 * NPTS + ii2] - sup[1 * MPTS + m];
                float p2 = pos[2 * NPTS + ii2] - sup[2 * MPTS + m];
                uint4 c8;
                c8.x = packh2(p0, p1);
                c8.y = packh2(p2, 1.0f);
                c8.z = 0u; c8.w = 0u;
                uint4 zz = make_uint4(0u, 0u, 0u, 0u);
                *(uint4*)(smc + SM_B1 + tid * 176 + 128) = c8;
                *(uint4*)(smc + SM_B1 + tid * 176 + 144) = zz;
            }
            CP_WAIT0();
        }
        __syncthreads();

        // ================= GEMM1: 64 x 128, K=80 (bias+pos folded) =========
        {
            float acc[2][4][4];
#pragma unroll
            for (int i = 0; i < 2; i++)
#pragma unroll
                for (int j = 0; j < 4; j++)
#pragma unroll
                    for (int q = 0; q < 4; q++) acc[i][j][q] = 0.0f;

#pragma unroll
            for (int ks = 0; ks < 5; ks++) {
                uint32_t ach = (2 * ks + (l >> 4)) * 16;
                uint32_t bch = (2 * ks + ((l >> 3) & 1)) * 16;
                uint32_t a0[4], a1[4], b0[4], b1r[4];
                ldsm4(a0, arow1 + ach);
                ldsm4(a1, arow1 + 16 * 176 + ach);
                ldsm4(b0, brow1 + bch);
                ldsm4(b1r, brow1 + 16 * 176 + bch);
                mma_f32(acc[0][0], a0, b0[0], b0[1]);
                mma_f32(acc[0][1], a0, b0[2], b0[3]);
                mma_f32(acc[0][2], a0, b1r[0], b1r[1]);
                mma_f32(acc[0][3], a0, b1r[2], b1r[3]);
                mma_f32(acc[1][0], a1, b0[0], b0[1]);
                mma_f32(acc[1][1], a1, b0[2], b0[3]);
                mma_f32(acc[1][2], a1, b1r[0], b1r[1]);
                mma_f32(acc[1][3], a1, b1r[2], b1r[3]);
            }

            // ---- epilogue: relu -> fp16 -> H ----
#pragma unroll
            for (int mb = 0; mb < 2; mb++) {
                int clo = ch_lo + mb * 16;
#pragma unroll
                for (int nb = 0; nb < 4; nb++) {
                    int cb = 32 * (w >> 1) + nb * 8 + (l & 3) * 2;
                    float v0 = fmaxf(acc[mb][nb][0], 0.0f);
                    float v1 = fmaxf(acc[mb][nb][1], 0.0f);
                    float v2 = fmaxf(acc[mb][nb][2], 0.0f);
                    float v3 = fmaxf(acc[mb][nb][3], 0.0f);
                    uint32_t u0 = (uint32_t)__half_as_ushort(__float2half_rn(v0));
                    uint32_t u1 = (uint32_t)__half_as_ushort(__float2half_rn(v1));
                    uint32_t u2 = (uint32_t)__half_as_ushort(__float2half_rn(v2));
                    uint32_t u3 = (uint32_t)__half_as_ushort(__float2half_rn(v3));
                    uint32_t p0 = __shfl_xor_sync(0xffffffffu, u0, 4);
                    uint32_t p1 = __shfl_xor_sync(0xffffffffu, u1, 4);
                    uint32_t p2 = __shfl_xor_sync(0xffffffffu, u2, 4);
                    uint32_t p3 = __shfl_xor_sync(0xffffffffu, u3, 4);
                    if (paired) {
                        uint32_t o0 = (uint32_t)cb * 144 + (uint32_t)clo * 2;
                        uint32_t o1 = o0 + 144;
                        *(uint32_t*)(smc + SM_H + o0)      = u0 | (p0 << 16);
                        *(uint32_t*)(smc + SM_H + o1)      = u1 | (p1 << 16);
                        *(uint32_t*)(smc + SM_H + o0 + 16) = u2 | (p2 << 16); // ch+8
                        *(uint32_t*)(smc + SM_H + o1 + 16) = u3 | (p3 << 16);
                    }
                }
            }
        }
        __syncthreads();

        // ================= GEMM2: 128 x 128, K=64 + max-pool ===============
        {
            float acc[2][8][4];
#pragma unroll
            for (int i = 0; i < 2; i++)
#pragma unroll
                for (int j = 0; j < 8; j++)
#pragma unroll
                    for (int q = 0; q < 4; q++) acc[i][j][q] = 0.0f;

#pragma unroll
            for (int ks = 0; ks < 4; ks++) {
                uint32_t ach = (2 * ks + (l >> 4)) * 16;
                uint32_t bch = (2 * ks + ((l >> 3) & 1)) * 16;
                uint32_t a0[4], a1[4];
                ldsm4(a0, arow2 + ach);
                ldsm4(a1, arow2 + 16 * 144 + ach);
#pragma unroll
                for (int nbq = 0; nbq < 4; nbq++) {
                    uint32_t b[4];
                    ldsm4(b, brow2 + nbq * (16 * 144) + bch);
                    mma_f32(acc[0][2 * nbq],     a0, b[0], b[1]);
                    mma_f32(acc[0][2 * nbq + 1], a0, b[2], b[3]);
                    mma_f32(acc[1][2 * nbq],     a1, b[0], b[1]);
                    mma_f32(acc[1][2 * nbq + 1], a1, b[2], b[3]);
                }
            }

            // ---- pool over K=16 cols per point ----
#pragma unroll
            for (int mb = 0; mb < 2; mb++) {
#pragma unroll
                for (int pt = 0; pt < 4; pt++) {
                    float m0 = fmaxf(fmaxf(acc[mb][2 * pt][0], acc[mb][2 * pt][1]),
                                     fmaxf(acc[mb][2 * pt + 1][0], acc[mb][2 * pt + 1][1]));
                    float m1 = fmaxf(fmaxf(acc[mb][2 * pt][2], acc[mb][2 * pt][3]),
                                     fmaxf(acc[mb][2 * pt + 1][2], acc[mb][2 * pt + 1][3]));
                    m0 = fmaxf(m0, __shfl_xor_sync(0xffffffffu, m0, 1));
                    m0 = fmaxf(m0, __shfl_xor_sync(0xffffffffu, m0, 2));
                    m1 = fmaxf(m1, __shfl_xor_sync(0xffffffffu, m1, 1));
                    m1 = fmaxf(m1, __shfl_xor_sync(0xffffffffu, m1, 2));
                    if ((l & 3) == 0) {
                        int row = 32 * (w & 3) + 16 * mb + (l >> 2);
                        int mp  = 4 * (w >> 2) + pt;
                        poolf[row * 12 + mp]       = m0;
                        poolf[(row + 8) * 12 + mp] = m1;
                    }
                }
            }
        }
        __syncthreads();

        // ---- coalesced output: [o][m], +b2 ----
        {
            int o = tid >> 1, mg = tid & 1;
            float4 v = *(const float4*)(poolf + o * 12 + mg * 4);
            v.x += bb_out; v.y += bb_out; v.z += bb_out; v.w += bb_out;
            *(float4*)(out + (size_t)o * MPTS + tile * 8 + mg * 4) = v;
        }
        __syncthreads();
    }
}

// ---------------------------------------------------------------------------
extern "C" void kernel_launch(void* const* d_in, const int* in_sizes, int n_in,
                              void* d_out, int out_size)
{
    const float *x = 0, *pos = 0, *sup = 0, *W1 = 0, *b1 = 0, *W2 = 0, *b2 = 0;
    const void* idx = 0;
    for (int i = 0; i < n_in; i++) {
        switch (in_sizes[i]) {
            case 4194304: x  = (const float*)d_in[i]; break;
            case 196608:  if (!pos) pos = (const float*)d_in[i];
                          else      sup = (const float*)d_in[i]; break;
            case 4288:    W1 = (const float*)d_in[i]; break;
            case 64:      b1 = (const float*)d_in[i]; break;
            case 8192:    W2 = (const float*)d_in[i]; break;
            case 128:     b2 = (const float*)d_in[i]; break;
            case 1048576: idx = d_in[i]; break;
            default: break;
        }
    }
    float* out = (float*)d_out;

    prep_all_kernel<<<NPTS / 128, 256>>>(x, W1, b1, W2, (const unsigned int*)idx);

    cudaFuncSetAttribute(pointnet_mma_kernel,
                         cudaFuncAttributeMaxDynamicSharedMemorySize, SM_TOTAL);
    pointnet_mma_kernel<<<GRID, 256, SM_TOTAL>>>(pos, sup, b2, idx, out);
}

// round 10
// speedup vs baseline: 2.6147x; 1.2214x over previous
#include <cuda_runtime.h>
#include <cuda_fp16.h>
#include <cstdint>

#define NPTS 65536
#define MPTS 65536
#define KNB  16
#define TILE 128              // columns per CTA tile (8 pts x 16 nbrs)
#define NTILES 8192
#define GRID 296              // 2 CTAs per SM

// ---------------- device scratch ----------------
__device__ __align__(16) unsigned short g_x[(size_t)NPTS * 64];    // fp16 rows 128B
__device__ __align__(16) unsigned short g_w1e[64 * 80];            // W1|pos|bias|pad
__device__ __align__(16) unsigned short g_w2[128 * 64];
__device__ int g_idx_is64;

// ---------------- smem layout (bytes) ----------------
#define SM_W1   0                      // 64 * 176 = 11264
#define SM_W2   11264                  // 128 * 144 = 18432
#define SM_B1   29696                  // 128 * 176 = 22528
#define SM_H    52224                  // 128 * 144 = 18432
#define SM_POOL 70656                  // 128 * 12 * 4 = 6144
#define SM_TOTAL 76800

// ---------------- helpers ----------------
__device__ __forceinline__ uint32_t smem_u32(const void* p) {
    uint32_t a;
    asm("{ .reg .u64 t; cvta.to.shared.u64 t, %1; cvt.u32.u64 %0, t; }" : "=r"(a) : "l"(p));
    return a;
}
__device__ __forceinline__ void ldsm4(uint32_t (&r)[4], uint32_t addr) {
    asm volatile("ldmatrix.sync.aligned.m8n8.x4.shared.b16 {%0,%1,%2,%3}, [%4];"
                 : "=r"(r[0]), "=r"(r[1]), "=r"(r[2]), "=r"(r[3]) : "r"(addr));
}
__device__ __forceinline__ void stsm4t(uint32_t addr, uint32_t r0, uint32_t r1,
                                       uint32_t r2, uint32_t r3) {
    asm volatile("stmatrix.sync.aligned.m8n8.x4.trans.shared.b16 [%0], {%1,%2,%3,%4};"
                 :: "r"(addr), "r"(r0), "r"(r1), "r"(r2), "r"(r3) : "memory");
}
__device__ __forceinline__ void mma_f32(float (&d)[4], const uint32_t (&a)[4],
                                        uint32_t b0, uint32_t b1) {
    asm volatile("mma.sync.aligned.m16n8k16.row.col.f32.f16.f16.f32 "
                 "{%0,%1,%2,%3}, {%4,%5,%6,%7}, {%8,%9}, {%0,%1,%2,%3};"
                 : "+f"(d[0]), "+f"(d[1]), "+f"(d[2]), "+f"(d[3])
                 : "r"(a[0]), "r"(a[1]), "r"(a[2]), "r"(a[3]), "r"(b0), "r"(b1));
}
#define CP16(dst, src) \
    asm volatile("cp.async.cg.shared.global [%0], [%1], 16;" :: "r"(dst), "l"(src))
#define CP_COMMIT()  asm volatile("cp.async.commit_group;" ::: "memory")
#define CP_WAIT0()   asm volatile("cp.async.wait_group 0;" ::: "memory")

__device__ __forceinline__ uint32_t packh2(float a, float b) {
    __half2 h = __floats2half2_rn(a, b);
    return *(uint32_t*)&h;
}

// ---------------- prep ----------------
__global__ __launch_bounds__(256) void prep_all_kernel(const float* __restrict__ x,
                                                       const float* __restrict__ W1,
                                                       const float* __restrict__ b1,
                                                       const float* __restrict__ W2,
                                                       const unsigned int* __restrict__ idx32)
{
    __shared__ unsigned short shhi[128 * 72];
    const int p0 = blockIdx.x * 128;
    const int tid = threadIdx.x;

    for (int idx = tid; idx < 128 * 64; idx += 256) {
        int c = idx >> 7, p = idx & 127;
        float v = x[(size_t)c * NPTS + p0 + p];
        shhi[p * 72 + c] = __half_as_ushort(__float2half_rn(v));
    }

    if (blockIdx.x == 0) {
        if (tid == 0) {
            unsigned int orv = 0;
            for (int i = 0; i < 256; i++) orv |= idx32[2 * i + 1];
            g_idx_is64 = (orv == 0u) ? 1 : 0;
        }
        for (int i = tid; i < 64 * 80; i += 256) {
            int o = i / 80, c = i % 80;
            float v = 0.0f;
            if (c < 67)       v = W1[o * 67 + c];
            else if (c == 67) v = b1[o];
            g_w1e[i] = __half_as_ushort(__float2half_rn(v));
        }
        for (int i = tid; i < 128 * 64; i += 256)
            g_w2[i] = __half_as_ushort(__float2half_rn(W2[i]));
    }
    __syncthreads();
    uint4* dh = (uint4*)(g_x + (size_t)p0 * 64);
    for (int i = tid; i < 1024; i += 256) {
        int p = i >> 3, q = i & 7;
        dh[i] = *(const uint4*)&shhi[p * 72 + q * 8];
    }
}

// ---------------- main persistent kernel: 256 thr, 2 CTAs/SM ----------------
extern __shared__ char smc[];

__global__ __launch_bounds__(256, 2)
void pointnet_mma_kernel(const float* __restrict__ pos,
                         const float* __restrict__ sup,
                         const float* __restrict__ b2,
                         const void* __restrict__ indices,
                         float* __restrict__ out)
{
    const uint32_t sb = smem_u32(smc);
    const int tid = threadIdx.x;
    const int w = tid >> 5;
    const int l = tid & 31;
    const int is64 = g_idx_is64;

    // ---- stage weights once ----
    for (int i = tid; i < 640; i += 256) {            // W1e: 64 rows x 10 chunks
        int o = i / 10, c = i % 10;
        *(uint4*)(smc + SM_W1 + o * 176 + c * 16) = *(const uint4*)(g_w1e + o * 80 + c * 8);
    }
    for (int i = tid; i < 1024; i += 256) {           // W2: 128 rows x 8 chunks
        int o = i >> 3, c = i & 7;
        *(uint4*)(smc + SM_W2 + o * 144 + c * 16) = *(const uint4*)(g_w2 + o * 64 + c * 8);
    }
    __syncthreads();

    float* poolf = (float*)(smc + SM_POOL);

    // ---- loop-invariant constants ----
    // GEMM1: mw=2 (w&1), nw=4 (w>>1)
    const uint32_t arow1 = sb + SM_W1 + (32 * (w & 1) + ((l >> 3) & 1) * 8 + (l & 7)) * 176;
    const uint32_t brow1 = sb + SM_B1 + (32 * (w >> 1) + ((l >> 4) & 1) * 8 + (l & 7)) * 176;
    // GEMM2: mw=4 (w&3), nw=2 (w>>2)
    const uint32_t arow2 = sb + SM_W2 + (32 * (w & 3) + ((l >> 3) & 1) * 8 + (l & 7)) * 144;
    const uint32_t brow2 = sb + SM_H  + (64 * (w >> 2) + ((l >> 4) & 1) * 8 + (l & 7)) * 144;
    // epilogue-1 stmatrix base: point row = n0 + 8*(l>>3) + (l&7)
    const uint32_t hst   = sb + SM_H + (32 * (w >> 1) + 8 * (l >> 3) + (l & 7)) * 144;

    const float bb_out = __ldg(&b2[tid >> 1]);
    const int gp   = tid >> 1;                        // gather row
    const int half = tid & 1;

    // ---- preload W2 A-fragments into registers (loop-invariant) ----
    uint32_t wa[4][2][4];
#pragma unroll
    for (int ks = 0; ks < 4; ks++) {
        uint32_t ach = (2 * ks + (l >> 4)) * 16;
        ldsm4(wa[ks][0], arow2 + ach);
        ldsm4(wa[ks][1], arow2 + 16 * 144 + ach);
    }

    int prev_tile = -1;

    for (int tile = blockIdx.x; tile < NTILES; tile += GRID) {
        // ===== phase A: gather new B1 + deferred output of previous tile =====
        {
            long long lin = (long long)tile * TILE + gp;
            int ii;
            if (is64) ii = (int)((const long long*)indices)[lin] & (NPTS - 1);
            else      ii = ((const int*)indices)[lin] & (NPTS - 1);
            const char* src = (const char*)g_x + (size_t)ii * 128;
            uint32_t dst = sb + SM_B1 + gp * 176 + half * 64;
#pragma unroll
            for (int q = 0; q < 4; q++)
                CP16(dst + q * 16, src + half * 64 + q * 16);
            CP_COMMIT();

            if (tid < TILE) {
                long long lin2 = (long long)tile * TILE + tid;
                int ii2;
                if (is64) ii2 = (int)((const long long*)indices)[lin2] & (NPTS - 1);
                else      ii2 = ((const int*)indices)[lin2] & (NPTS - 1);
                int m = tile * 8 + (tid >> 4);
                float p0 = pos[0 * NPTS + ii2] - sup[0 * MPTS + m];
                float p1 = pos[1 * NPTS + ii2] - sup[1 * MPTS + m];
                float p2 = pos[2 * NPTS + ii2] - sup[2 * MPTS + m];
                uint4 c8;
                c8.x = packh2(p0, p1);
                c8.y = packh2(p2, 1.0f);
                c8.z = 0u; c8.w = 0u;
                uint4 zz = make_uint4(0u, 0u, 0u, 0u);
                *(uint4*)(smc + SM_B1 + tid * 176 + 128) = c8;
                *(uint4*)(smc + SM_B1 + tid * 176 + 144) = zz;
            }

            if (prev_tile >= 0) {
                int o = tid >> 1, mg = tid & 1;
                float4 v = *(const float4*)(poolf + o * 12 + mg * 4);
                v.x += bb_out; v.y += bb_out; v.z += bb_out; v.w += bb_out;
                *(float4*)(out + (size_t)o * MPTS + prev_tile * 8 + mg * 4) = v;
            }
            CP_WAIT0();
        }
        __syncthreads();

        // ===== GEMM1: 64 x 128, K=80 (bias+pos folded) =====
        {
            float acc[2][4][4];
#pragma unroll
            for (int i = 0; i < 2; i++)
#pragma unroll
                for (int j = 0; j < 4; j++)
#pragma unroll
                    for (int q = 0; q < 4; q++) acc[i][j][q] = 0.0f;

#pragma unroll
            for (int ks = 0; ks < 5; ks++) {
                uint32_t ach = (2 * ks + (l >> 4)) * 16;
                uint32_t bch = (2 * ks + ((l >> 3) & 1)) * 16;
                uint32_t a0[4], a1[4], b0[4], b1r[4];
                ldsm4(a0, arow1 + ach);
                ldsm4(a1, arow1 + 16 * 176 + ach);
                ldsm4(b0, brow1 + bch);
                ldsm4(b1r, brow1 + 16 * 176 + bch);
                mma_f32(acc[0][0], a0, b0[0], b0[1]);
                mma_f32(acc[0][1], a0, b0[2], b0[3]);
                mma_f32(acc[0][2], a0, b1r[0], b1r[1]);
                mma_f32(acc[0][3], a0, b1r[2], b1r[3]);
                mma_f32(acc[1][0], a1, b0[0], b0[1]);
                mma_f32(acc[1][1], a1, b0[2], b0[3]);
                mma_f32(acc[1][2], a1, b1r[0], b1r[1]);
                mma_f32(acc[1][3], a1, b1r[2], b1r[3]);
            }

            // ---- epilogue: relu -> fp16 -> H via stmatrix.trans ----
#pragma unroll
            for (int mb = 0; mb < 2; mb++) {
#pragma unroll
                for (int hf = 0; hf < 2; hf++) {
                    uint32_t r[4];
#pragma unroll
                    for (int nb = 0; nb < 4; nb++) {
                        float v0 = fmaxf(acc[mb][nb][2 * hf], 0.0f);
                        float v1 = fmaxf(acc[mb][nb][2 * hf + 1], 0.0f);
                        r[nb] = packh2(v0, v1);
                    }
                    uint32_t ch = 32 * (w & 1) + 16 * mb + 8 * hf;
                    stsm4t(hst + ch * 2, r[0], r[1], r[2], r[3]);
                }
            }
        }
        __syncthreads();

        // ===== GEMM2: 128 x 128, K=64 (W2 in regs) + max-pool =====
        {
            float acc[2][8][4];
#pragma unroll
            for (int i = 0; i < 2; i++)
#pragma unroll
                for (int j = 0; j < 8; j++)
#pragma unroll
                    for (int q = 0; q < 4; q++) acc[i][j][q] = 0.0f;

#pragma unroll
            for (int ks = 0; ks < 4; ks++) {
                uint32_t bch = (2 * ks + ((l >> 3) & 1)) * 16;
#pragma unroll
                for (int nbq = 0; nbq < 4; nbq++) {
                    uint32_t b[4];
                    ldsm4(b, brow2 + nbq * (16 * 144) + bch);
                    mma_f32(acc[0][2 * nbq],     wa[ks][0], b[0], b[1]);
                    mma_f32(acc[0][2 * nbq + 1], wa[ks][0], b[2], b[3]);
                    mma_f32(acc[1][2 * nbq],     wa[ks][1], b[0], b[1]);
                    mma_f32(acc[1][2 * nbq + 1], wa[ks][1], b[2], b[3]);
                }
            }

            // ---- pool over K=16 cols per point ----
#pragma unroll
            for (int mb = 0; mb < 2; mb++) {
#pragma unroll
                for (int pt = 0; pt < 4; pt++) {
                    float m0 = fmaxf(fmaxf(acc[mb][2 * pt][0], acc[mb][2 * pt][1]),
                                     fmaxf(acc[mb][2 * pt + 1][0], acc[mb][2 * pt + 1][1]));
                    float m1 = fmaxf(fmaxf(acc[mb][2 * pt][2], acc[mb][2 * pt][3]),
                                     fmaxf(acc[mb][2 * pt + 1][2], acc[mb][2 * pt + 1][3]));
                    m0 = fmaxf(m0, __shfl_xor_sync(0xffffffffu, m0, 1));
                    m0 = fmaxf(m0, __shfl_xor_sync(0xffffffffu, m0, 2));
                    m1 = fmaxf(m1, __shfl_xor_sync(0xffffffffu, m1, 1));
                    m1 = fmaxf(m1, __shfl_xor_sync(0xffffffffu, m1, 2));
                    if ((l & 3) == 0) {
                        int row = 32 * (w & 3) + 16 * mb + (l >> 2);
                        int mp  = 4 * (w >> 2) + pt;
                        poolf[row * 12 + mp]       = m0;
                        poolf[(row + 8) * 12 + mp] = m1;
                    }
                }
            }
        }
        prev_tile = tile;
        __syncthreads();
    }

    // ---- final deferred output ----
    if (prev_tile >= 0) {
        int o = tid >> 1, mg = tid & 1;
        float4 v = *(const float4*)(poolf + o * 12 + mg * 4);
        v.x += bb_out; v.y += bb_out; v.z += bb_out; v.w += bb_out;
        *(float4*)(out + (size_t)o * MPTS + prev_tile * 8 + mg * 4) = v;
    }
}

// ---------------------------------------------------------------------------
extern "C" void kernel_launch(void* const* d_in, const int* in_sizes, int n_in,
                              void* d_out, int out_size)
{
    const float *x = 0, *pos = 0, *sup = 0, *W1 = 0, *b1 = 0, *W2 = 0, *b2 = 0;
    const void* idx = 0;
    for (int i = 0; i < n_in; i++) {
        switch (in_sizes[i]) {
            case 4194304: x  = (const float*)d_in[i]; break;
            case 196608:  if (!pos) pos = (const float*)d_in[i];
                          else      sup = (const float*)d_in[i]; break;
            case 4288:    W1 = (const float*)d_in[i]; break;
            case 64:      b1 = (const float*)d_in[i]; break;
            case 8192:    W2 = (const float*)d_in[i]; break;
            case 128:     b2 = (const float*)d_in[i]; break;
            case 1048576: idx = d_in[i]; break;
            default: break;
        }
    }
    float* out = (float*)d_out;

    prep_all_kernel<<<NPTS / 128, 256>>>(x, W1, b1, W2, (const unsigned int*)idx);

    cudaFuncSetAttribute(pointnet_mma_kernel,
                         cudaFuncAttributeMaxDynamicSharedMemorySize, SM_TOTAL);
    pointnet_mma_kernel<<<GRID, 256, SM_TOTAL>>>(pos, sup, b2, idx, out);
}

// round 11
// speedup vs baseline: 2.7661x; 1.0579x over previous
#include <cuda_runtime.h>
#include <cuda_fp16.h>
#include <cstdint>

#define NPTS 65536
#define MPTS 65536
#define KNB  16
#define TILE 128              // columns per CTA tile (8 pts x 16 nbrs)
#define NTILES 8192
#define GRID 296              // 2 CTAs per SM

// ---------------- device scratch ----------------
__device__ __align__(16) unsigned short g_x[(size_t)NPTS * 64];    // fp16 rows 128B
__device__ __align__(16) unsigned short g_w1e[64 * 80];            // W1|pos|bias|pad
__device__ __align__(16) unsigned short g_w2[128 * 64];
__device__ int g_idx_is64;

// ---------------- smem layout (bytes) ----------------
#define SM_W1   0                      // 64 * 176  = 11264
#define SM_W2   11264                  // 128 * 144 = 18432
#define SM_B1A  29696                  // 128 * 176 = 22528
#define SM_B1B  52224                  // 128 * 176 = 22528
#define SM_H    74752                  // 128 * 144 = 18432
#define SM_POOL 93184                  // 128 * 12 * 4 = 6144
#define SM_TOTAL 99328

// ---------------- helpers ----------------
__device__ __forceinline__ uint32_t smem_u32(const void* p) {
    uint32_t a;
    asm("{ .reg .u64 t; cvta.to.shared.u64 t, %1; cvt.u32.u64 %0, t; }" : "=r"(a) : "l"(p));
    return a;
}
__device__ __forceinline__ void ldsm4(uint32_t (&r)[4], uint32_t addr) {
    asm volatile("ldmatrix.sync.aligned.m8n8.x4.shared.b16 {%0,%1,%2,%3}, [%4];"
                 : "=r"(r[0]), "=r"(r[1]), "=r"(r[2]), "=r"(r[3]) : "r"(addr));
}
__device__ __forceinline__ void stsm4t(uint32_t addr, uint32_t r0, uint32_t r1,
                                       uint32_t r2, uint32_t r3) {
    asm volatile("stmatrix.sync.aligned.m8n8.x4.trans.shared.b16 [%0], {%1,%2,%3,%4};"
                 :: "r"(addr), "r"(r0), "r"(r1), "r"(r2), "r"(r3) : "memory");
}
__device__ __forceinline__ void mma_f32(float (&d)[4], const uint32_t (&a)[4],
                                        uint32_t b0, uint32_t b1) {
    asm volatile("mma.sync.aligned.m16n8k16.row.col.f32.f16.f16.f32 "
                 "{%0,%1,%2,%3}, {%4,%5,%6,%7}, {%8,%9}, {%0,%1,%2,%3};"
                 : "+f"(d[0]), "+f"(d[1]), "+f"(d[2]), "+f"(d[3])
                 : "r"(a[0]), "r"(a[1]), "r"(a[2]), "r"(a[3]), "r"(b0), "r"(b1));
}
#define CP16(dst, src) \
    asm volatile("cp.async.cg.shared.global [%0], [%1], 16;" :: "r"(dst), "l"(src))
#define CP_COMMIT()  asm volatile("cp.async.commit_group;" ::: "memory")
#define CP_WAIT0()   asm volatile("cp.async.wait_group 0;" ::: "memory")

__device__ __forceinline__ uint32_t packh2(float a, float b) {
    __half2 h = __floats2half2_rn(a, b);
    return *(uint32_t*)&h;
}

// ---------------- prep ----------------
__global__ __launch_bounds__(256) void prep_all_kernel(const float* __restrict__ x,
                                                       const float* __restrict__ W1,
                                                       const float* __restrict__ b1,
                                                       const float* __restrict__ W2,
                                                       const unsigned int* __restrict__ idx32)
{
    __shared__ unsigned short shhi[128 * 72];
    const int p0 = blockIdx.x * 128;
    const int tid = threadIdx.x;

    for (int idx = tid; idx < 128 * 64; idx += 256) {
        int c = idx >> 7, p = idx & 127;
        float v = x[(size_t)c * NPTS + p0 + p];
        shhi[p * 72 + c] = __half_as_ushort(__float2half_rn(v));
    }

    if (blockIdx.x == 0) {
        if (tid == 0) {
            unsigned int orv = 0;
            for (int i = 0; i < 256; i++) orv |= idx32[2 * i + 1];
            g_idx_is64 = (orv == 0u) ? 1 : 0;
        }
        for (int i = tid; i < 64 * 80; i += 256) {
            int o = i / 80, c = i % 80;
            float v = 0.0f;
            if (c < 67)       v = W1[o * 67 + c];
            else if (c == 67) v = b1[o];
            g_w1e[i] = __half_as_ushort(__float2half_rn(v));
        }
        for (int i = tid; i < 128 * 64; i += 256)
            g_w2[i] = __half_as_ushort(__float2half_rn(W2[i]));
    }
    __syncthreads();
    uint4* dh = (uint4*)(g_x + (size_t)p0 * 64);
    for (int i = tid; i < 1024; i += 256) {
        int p = i >> 3, q = i & 7;
        dh[i] = *(const uint4*)&shhi[p * 72 + q * 8];
    }
}

// ---------------- main persistent kernel: 256 thr, 2 CTAs/SM ----------------
extern __shared__ char smc[];

__global__ __launch_bounds__(256, 2)
void pointnet_mma_kernel(const float* __restrict__ pos,
                         const float* __restrict__ sup,
                         const float* __restrict__ b2,
                         const void* __restrict__ indices,
                         float* __restrict__ out)
{
    const uint32_t sb = smem_u32(smc);
    const int tid = threadIdx.x;
    const int w = tid >> 5;
    const int l = tid & 31;
    const int is64 = g_idx_is64;

    // ---- stage weights once ----
    for (int i = tid; i < 640; i += 256) {            // W1e: 64 rows x 10 chunks
        int o = i / 10, c = i % 10;
        *(uint4*)(smc + SM_W1 + o * 176 + c * 16) = *(const uint4*)(g_w1e + o * 80 + c * 8);
    }
    for (int i = tid; i < 1024; i += 256) {           // W2: 128 rows x 8 chunks
        int o = i >> 3, c = i & 7;
        *(uint4*)(smc + SM_W2 + o * 144 + c * 16) = *(const uint4*)(g_w2 + o * 64 + c * 8);
    }
    __syncthreads();

    float* poolf = (float*)(smc + SM_POOL);

    // ---- loop-invariant constants ----
    const uint32_t arow1 = sb + SM_W1 + (32 * (w & 1) + ((l >> 3) & 1) * 8 + (l & 7)) * 176;
    const uint32_t boff1 = (uint32_t)(32 * (w >> 1) + ((l >> 4) & 1) * 8 + (l & 7)) * 176;
    const uint32_t arow2 = sb + SM_W2 + (32 * (w & 3) + ((l >> 3) & 1) * 8 + (l & 7)) * 144;
    const uint32_t brow2 = sb + SM_H  + (64 * (w >> 2) + ((l >> 4) & 1) * 8 + (l & 7)) * 144;
    const uint32_t hst   = sb + SM_H + (32 * (w >> 1) + 8 * (l >> 3) + (l & 7)) * 144;

    const float bb_out = __ldg(&b2[tid >> 1]);
    const int gp   = tid >> 1;
    const int half = tid & 1;

    auto load_idx = [&](long long lin) -> int {
        if (is64) return (int)((const long long*)indices)[lin] & (NPTS - 1);
        return ((const int*)indices)[lin] & (NPTS - 1);
    };

    // ---- preload W2 A-fragments into registers (loop-invariant) ----
    uint32_t wa[4][2][4];
#pragma unroll
    for (int ks = 0; ks < 4; ks++) {
        uint32_t ach = (2 * ks + (l >> 4)) * 16;
        ldsm4(wa[ks][0], arow2 + ach);
        ldsm4(wa[ks][1], arow2 + 16 * 144 + ach);
    }

    // ---- prologue: synchronous gather of tile0 into B1A ----
    const int tile0 = blockIdx.x;
    {
        int ii = load_idx((long long)tile0 * TILE + gp);
        const char* src = (const char*)g_x + (size_t)ii * 128;
        uint32_t dst = sb + SM_B1A + gp * 176 + half * 64;
#pragma unroll
        for (int q = 0; q < 4; q++)
            CP16(dst + q * 16, src + half * 64 + q * 16);
        CP_COMMIT();
        if (tid < TILE) {
            int ii2 = load_idx((long long)tile0 * TILE + tid);
            int m = tile0 * 8 + (tid >> 4);
            float p0 = pos[0 * NPTS + ii2] - sup[0 * MPTS + m];
            float p1 = pos[1 * NPTS + ii2] - sup[1 * MPTS + m];
            float p2 = pos[2 * NPTS + ii2] - sup[2 * MPTS + m];
            uint4 c8;
            c8.x = packh2(p0, p1);
            c8.y = packh2(p2, 1.0f);
            c8.z = 0u; c8.w = 0u;
            uint4 zz = make_uint4(0u, 0u, 0u, 0u);
            *(uint4*)(smc + SM_B1A + tid * 176 + 128) = c8;
            *(uint4*)(smc + SM_B1A + tid * 176 + 144) = zz;
        }
        CP_WAIT0();
    }
    __syncthreads();

    int bufsel = 0;
    for (int tile = tile0; tile < NTILES; tile += GRID) {
        const uint32_t curB = bufsel ? SM_B1B : SM_B1A;
        const uint32_t nxtB = bufsel ? SM_B1A : SM_B1B;
        int pf = tile + GRID;
        if (pf >= NTILES) pf = tile;                  // safe redundant prefetch

        // prefetch indices for tile+GRID (latency hidden by GEMM1)
        int ii_nx = load_idx((long long)pf * TILE + gp);
        int ii_pd = 0;
        if (tid < TILE) ii_pd = load_idx((long long)pf * TILE + tid);

        // ===== GEMM1: 64 x 128, K=80 (bias+pos folded) =====
        {
            const uint32_t brow1 = sb + curB + boff1;
            float acc[2][4][4];
#pragma unroll
            for (int i = 0; i < 2; i++)
#pragma unroll
                for (int j = 0; j < 4; j++)
#pragma unroll
                    for (int q = 0; q < 4; q++) acc[i][j][q] = 0.0f;

#pragma unroll
            for (int ks = 0; ks < 5; ks++) {
                uint32_t ach = (2 * ks + (l >> 4)) * 16;
                uint32_t bch = (2 * ks + ((l >> 3) & 1)) * 16;
                uint32_t a0[4], a1[4], b0[4], b1r[4];
                ldsm4(a0, arow1 + ach);
                ldsm4(a1, arow1 + 16 * 176 + ach);
                ldsm4(b0, brow1 + bch);
                ldsm4(b1r, brow1 + 16 * 176 + bch);
                mma_f32(acc[0][0], a0, b0[0], b0[1]);
                mma_f32(acc[0][1], a0, b0[2], b0[3]);
                mma_f32(acc[0][2], a0, b1r[0], b1r[1]);
                mma_f32(acc[0][3], a0, b1r[2], b1r[3]);
                mma_f32(acc[1][0], a1, b0[0], b0[1]);
                mma_f32(acc[1][1], a1, b0[2], b0[3]);
                mma_f32(acc[1][2], a1, b1r[0], b1r[1]);
                mma_f32(acc[1][3], a1, b1r[2], b1r[3]);
            }

            // ---- issue async gather of next tile into B1[nxt] ----
            {
                const char* src = (const char*)g_x + (size_t)ii_nx * 128;
                uint32_t dst = sb + nxtB + gp * 176 + half * 64;
#pragma unroll
                for (int q = 0; q < 4; q++)
                    CP16(dst + q * 16, src + half * 64 + q * 16);
                CP_COMMIT();
            }

            // ---- epilogue: relu -> fp16 -> H via stmatrix.trans ----
#pragma unroll
            for (int mb = 0; mb < 2; mb++) {
#pragma unroll
                for (int hf = 0; hf < 2; hf++) {
                    uint32_t r[4];
#pragma unroll
                    for (int nb = 0; nb < 4; nb++) {
                        float v0 = fmaxf(acc[mb][nb][2 * hf], 0.0f);
                        float v1 = fmaxf(acc[mb][nb][2 * hf + 1], 0.0f);
                        r[nb] = packh2(v0, v1);
                    }
                    uint32_t ch = 32 * (w & 1) + 16 * mb + 8 * hf;
                    stsm4t(hst + ch * 2, r[0], r[1], r[2], r[3]);
                }
            }
        }
        __syncthreads();

        // ===== GEMM2: 128 x 128, K=64 (W2 in regs) + max-pool =====
        {
            // pos/sup loads for next tile issue here; latency hidden by k-loop
            float p0 = 0.f, p1 = 0.f, p2 = 0.f;
            if (tid < TILE) {
                int m = pf * 8 + (tid >> 4);
                p0 = pos[0 * NPTS + ii_pd] - sup[0 * MPTS + m];
                p1 = pos[1 * NPTS + ii_pd] - sup[1 * MPTS + m];
                p2 = pos[2 * NPTS + ii_pd] - sup[2 * MPTS + m];
            }

            float acc[2][8][4];
#pragma unroll
            for (int i = 0; i < 2; i++)
#pragma unroll
                for (int j = 0; j < 8; j++)
#pragma unroll
                    for (int q = 0; q < 4; q++) acc[i][j][q] = 0.0f;

#pragma unroll
            for (int ks = 0; ks < 4; ks++) {
                uint32_t bch = (2 * ks + ((l >> 3) & 1)) * 16;
#pragma unroll
                for (int nbq = 0; nbq < 4; nbq++) {
                    uint32_t b[4];
                    ldsm4(b, brow2 + nbq * (16 * 144) + bch);
                    mma_f32(acc[0][2 * nbq],     wa[ks][0], b[0], b[1]);
                    mma_f32(acc[0][2 * nbq + 1], wa[ks][0], b[2], b[3]);
                    mma_f32(acc[1][2 * nbq],     wa[ks][1], b[0], b[1]);
                    mma_f32(acc[1][2 * nbq + 1], wa[ks][1], b[2], b[3]);
                }
            }

            // ---- pool over K=16 cols per point ----
#pragma unroll
            for (int mb = 0; mb < 2; mb++) {
#pragma unroll
                for (int pt = 0; pt < 4; pt++) {
                    float m0 = fmaxf(fmaxf(acc[mb][2 * pt][0], acc[mb][2 * pt][1]),
                                     fmaxf(acc[mb][2 * pt + 1][0], acc[mb][2 * pt + 1][1]));
                    float m1 = fmaxf(fmaxf(acc[mb][2 * pt][2], acc[mb][2 * pt][3]),
                                     fmaxf(acc[mb][2 * pt + 1][2], acc[mb][2 * pt + 1][3]));
                    m0 = fmaxf(m0, __shfl_xor_sync(0xffffffffu, m0, 1));
                    m0 = fmaxf(m0, __shfl_xor_sync(0xffffffffu, m0, 2));
                    m1 = fmaxf(m1, __shfl_xor_sync(0xffffffffu, m1, 1));
                    m1 = fmaxf(m1, __shfl_xor_sync(0xffffffffu, m1, 2));
                    if ((l & 3) == 0) {
                        int row = 32 * (w & 3) + 16 * mb + (l >> 2);
                        int mp  = 4 * (w >> 2) + pt;
                        poolf[row * 12 + mp]       = m0;
                        poolf[(row + 8) * 12 + mp] = m1;
                    }
                }
            }

            // ---- store next tile's pos channels into B1[nxt] ----
            if (tid < TILE) {
                uint4 c8;
                c8.x = packh2(p0, p1);
                c8.y = packh2(p2, 1.0f);
                c8.z = 0u; c8.w = 0u;
                uint4 zz = make_uint4(0u, 0u, 0u, 0u);
                *(uint4*)(smc + nxtB + tid * 176 + 128) = c8;
                *(uint4*)(smc + nxtB + tid * 176 + 144) = zz;
            }
        }
        __syncthreads();

        // ---- coalesced output: [o][m], +b2 ----
        {
            int o = tid >> 1, mg = tid & 1;
            float4 v = *(const float4*)(poolf + o * 12 + mg * 4);
            v.x += bb_out; v.y += bb_out; v.z += bb_out; v.w += bb_out;
            *(float4*)(out + (size_t)o * MPTS + tile * 8 + mg * 4) = v;
        }

        CP_WAIT0();                       // B1[nxt] gather complete
        __syncthreads();                  // publish B1[nxt] (+pd) to all warps
        bufsel ^= 1;
    }
}

// ---------------------------------------------------------------------------
extern "C" void kernel_launch(void* const* d_in, const int* in_sizes, int n_in,
                              void* d_out, int out_size)
{
    const float *x = 0, *pos = 0, *sup = 0, *W1 = 0, *b1 = 0, *W2 = 0, *b2 = 0;
    const void* idx = 0;
    for (int i = 0; i < n_in; i++) {
        switch (in_sizes[i]) {
            case 4194304: x  = (const float*)d_in[i]; break;
            case 196608:  if (!pos) pos = (const float*)d_in[i];
                          else      sup = (const float*)d_in[i]; break;
            case 4288:    W1 = (const float*)d_in[i]; break;
            case 64:      b1 = (const float*)d_in[i]; break;
            case 8192:    W2 = (const float*)d_in[i]; break;
            case 128:     b2 = (const float*)d_in[i]; break;
            case 1048576: idx = d_in[i]; break;
            default: break;
        }
    }
    float* out = (float*)d_out;

    prep_all_kernel<<<NPTS / 128, 256>>>(x, W1, b1, W2, (const unsigned int*)idx);

    cudaFuncSetAttribute(pointnet_mma_kernel,
                         cudaFuncAttributeMaxDynamicSharedMemorySize, SM_TOTAL);
    pointnet_mma_kernel<<<GRID, 256, SM_TOTAL>>>(pos, sup, b2, idx, out);
}